// round 14
// baseline (speedup 1.0000x reference)
#include <cuda_runtime.h>
#include <cstdint>

// celerite GP factor + solve + loglike. N=262144, J=16, R=4.
// Lane-split layout: 16 lanes per chunk, TWO chunks per warp (lane halves).
// Forward: cp.async double-buffered row staging into smem (zero-register
// prefetch); backward: distance-1 register prefetch at occupancy 3.

#define JDIM 16
#define RDIM 4
#define OV   8
#define NMAX 262144
#define MAXC 16384
#define FULLM 0xffffffffu

#define STG_F 112          // floats per stage per warp (448 B)
#define OFF_P 0            // P rows: half A at +0, half B at +16 floats
#define OFF_U 32
#define OFF_V 64
#define OFF_Y 96           // y: half A +96, half B +100
#define OFF_A 104          // a: half A +104, half B +108

typedef unsigned long long u64t;

__device__ float g_W[(size_t)NMAX * JDIM];
__device__ float g_z[(size_t)NMAX * RDIM];
__device__ float g_logd[MAXC];
__device__ float g_yx[MAXC * RDIM];

__device__ __forceinline__ float fast_rcp(float x) {
    float r;
    asm("rcp.approx.f32 %0, %1;" : "=f"(r) : "f"(x));
    r = r * (2.0f - x * r);
    return r;
}
__device__ __forceinline__ u64t pk2(float lo, float hi) {
    u64t r; asm("mov.b64 %0, {%1,%2};" : "=l"(r) : "f"(lo), "f"(hi)); return r;
}
__device__ __forceinline__ void upk2(u64t v, float& lo, float& hi) {
    asm("mov.b64 {%0,%1}, %2;" : "=f"(lo), "=f"(hi) : "l"(v));
}
__device__ __forceinline__ u64t mul2(u64t a, u64t b) {
    u64t r; asm("mul.rn.f32x2 %0, %1, %2;" : "=l"(r) : "l"(a), "l"(b)); return r;
}
__device__ __forceinline__ u64t add2(u64t a, u64t b) {
    u64t r; asm("add.rn.f32x2 %0, %1, %2;" : "=l"(r) : "l"(a), "l"(b)); return r;
}
__device__ __forceinline__ u64t fma2(u64t a, u64t b, u64t c) {
    u64t r; asm("fma.rn.f32x2 %0, %1, %2, %3;" : "=l"(r) : "l"(a), "l"(b), "l"(c)); return r;
}
__device__ __forceinline__ void cpa16(uint32_t d, const void* s) {
    asm volatile("cp.async.ca.shared.global [%0], [%1], 16;" :: "r"(d), "l"(s) : "memory");
}
__device__ __forceinline__ void cpa4(uint32_t d, const void* s) {
    asm volatile("cp.async.ca.shared.global [%0], [%1], 4;" :: "r"(d), "l"(s) : "memory");
}
__device__ __forceinline__ uint32_t smem_u32(const void* p) {
    uint32_t r;
    asm("{.reg .u64 t; cvta.to.shared.u64 t, %1; cvt.u32.u64 %0, t;}" : "=r"(r) : "l"(p));
    return r;
}

// ---------------------------------------------------------------------------
// Kernel 1: fused factorization + forward solve. 2 chunks/warp (lane halves).
// Rows staged via cp.async (depth-2 ring); compute reads them via LDS.
// ---------------------------------------------------------------------------
__global__ void __launch_bounds__(256, 3)
factor_forward_kernel(const float* __restrict__ a, const float* __restrict__ U,
                      const float* __restrict__ V, const float* __restrict__ P,
                      const float* __restrict__ y, int N, int C, int L)
{
    __shared__ __align__(16) float stg[8][2 * STG_F];

    int tid = threadIdx.x;
    int warp = (blockIdx.x * blockDim.x + tid) >> 5;
    int wloc = tid >> 5;
    int lane = tid & 31;
    int il  = lane & 15;
    int b16 = lane & 16;
    int half = lane >> 4;

    int chunk = 2 * warp + half;
    bool active = (chunk < C) && ((size_t)chunk * L < (size_t)N);
    int s = active ? chunk * L : 0;
    int e = min(s + L, N);
    int m0 = max(0, s - OV);
    int len = active ? (e - m0 - 1) : 0;
    int T = max(len, __shfl_xor_sync(FULLM, len, 16));

    // ---- init state at row m0 (direct LDG, one time)
    u64t S8[8];
    u64t fA, fB, zpA, zpB, wprevP;
    float llogd = 0.f;
    {
        float an = a[m0];
        float vi = V[(size_t)m0 * JDIM + il];
        float rd = fast_rcp(an);
        float wi = vi * rd;
        float wj[16];
#pragma unroll
        for (int j = 0; j < 16; j++) wj[j] = __shfl_sync(FULLM, wi, b16 + j);
        float dw = an * wi;
#pragma unroll
        for (int k = 0; k < 8; k++) S8[k] = pk2(dw * wj[2*k], dw * wj[2*k+1]);

        float4 y0 = *(const float4*)(y + (size_t)m0 * RDIM);
        zpA = pk2(y0.x, y0.y);
        zpB = pk2(y0.z, y0.w);
        fA = 0ull; fB = 0ull;
        wprevP = pk2(wi, wi);

        if (active && m0 == s) {   // chunk 0: store row 0
            g_W[(size_t)m0 * JDIM + il] = wi;
            if (il == 0) *(float4*)(g_z + (size_t)m0 * RDIM) =
                make_float4(y0.x * rd, y0.y * rd, y0.z * rd, y0.w * rd);
            llogd = __logf(an);
        }
    }

    // ---- cp.async role setup (per lane): which stream this lane stages
    int r1 = m0 + 1;
    const float* src;
    int strideF;
    int dstoff;
    bool c16 = true, c4 = false;
    if (il < 4)        { src = P + (size_t)m0 * JDIM + il * 4;       strideF = JDIM; dstoff = OFF_P + half*16 + il*4; }
    else if (il < 8)   { src = U + (size_t)r1 * JDIM + (il-4) * 4;   strideF = JDIM; dstoff = OFF_U + half*16 + (il-4)*4; }
    else if (il < 12)  { src = V + (size_t)r1 * JDIM + (il-8) * 4;   strideF = JDIM; dstoff = OFF_V + half*16 + (il-8)*4; }
    else if (il == 12) { src = y + (size_t)r1 * RDIM;                strideF = RDIM; dstoff = OFF_Y + half*4; }
    else if (il == 13) { src = a + r1; strideF = 1; c16 = false; c4 = true; dstoff = OFF_A + half*4; }
    else               { src = a; strideF = 0; c16 = false; dstoff = 0; }

    float* wsm = &stg[wloc][0];
    uint32_t wsmU = smem_u32(wsm);

    // ---- prologue: stage iterations 0 and 1
    {
        uint32_t d0 = wsmU + (uint32_t)(0 * STG_F + dstoff) * 4u;
        if (c16) cpa16(d0, src); else if (c4) cpa4(d0, src);
        asm volatile("cp.async.commit_group;" ::: "memory");
        src += (1 < len) ? strideF : 0;
        uint32_t d1 = wsmU + (uint32_t)(1 * STG_F + dstoff) * 4u;
        if (c16) cpa16(d1, src); else if (c4) cpa4(d1, src);
        asm volatile("cp.async.commit_group;" ::: "memory");
        src += (2 < len) ? strideF : 0;
    }

    float* pgW = g_W + (size_t)r1 * JDIM + il;
    float* pgz = g_z + (size_t)r1 * RDIM;
    int nrow = r1;

#pragma unroll 1
    for (int t = 0; t < T; t++) {
        asm volatile("cp.async.wait_group 1;" ::: "memory");
        __syncwarp();

        int sb = (t & 1) * STG_F;
        const float* sp  = wsm + sb;
        const float* spP = sp + OFF_P + half * 16;
        const float* spU = sp + OFF_U + half * 16;
        const float* spV = sp + OFF_V + half * 16;

        ulonglong2 pjA = *(const ulonglong2*)(spP);
        ulonglong2 pjB = *(const ulonglong2*)(spP + 4);
        ulonglong2 pjC = *(const ulonglong2*)(spP + 8);
        ulonglong2 pjD = *(const ulonglong2*)(spP + 12);
        float pi = spP[il];
        ulonglong2 ujA = *(const ulonglong2*)(spU);
        ulonglong2 ujB = *(const ulonglong2*)(spU + 4);
        ulonglong2 ujC = *(const ulonglong2*)(spU + 8);
        ulonglong2 ujD = *(const ulonglong2*)(spU + 12);
        float ui = spU[il];
        float vi = spV[il];
        float4 yv = *(const float4*)(sp + OFF_Y + half * 4);
        float an = sp[OFF_A + half * 4];

        __syncwarp();   // all lanes done reading stage sb before restaging it

        // stage iteration t+2 into the slot just consumed
        {
            uint32_t d = wsmU + (uint32_t)(sb + dstoff) * 4u;
            if (c16) cpa16(d, src); else if (c4) cpa4(d, src);
            asm volatile("cp.async.commit_group;" ::: "memory");
            src += (t + 3 < len) ? strideF : 0;
        }

        u64t pis = pk2(pi, pi);

        // F recurrence
        fA = mul2(pis, fma2(wprevP, zpA, fA));
        fB = mul2(pis, fma2(wprevP, zpB, fB));

        // S decay
        S8[0] = mul2(S8[0], mul2(pis, pjA.x));
        S8[1] = mul2(S8[1], mul2(pis, pjA.y));
        S8[2] = mul2(S8[2], mul2(pis, pjB.x));
        S8[3] = mul2(S8[3], mul2(pis, pjB.y));
        S8[4] = mul2(S8[4], mul2(pis, pjC.x));
        S8[5] = mul2(S8[5], mul2(pis, pjC.y));
        S8[6] = mul2(S8[6], mul2(pis, pjD.x));
        S8[7] = mul2(S8[7], mul2(pis, pjD.y));

        // su_i = S row . U row (lane-local)
        u64t q0 = mul2(S8[0], ujA.x), q1 = mul2(S8[1], ujA.y);
        u64t q2 = mul2(S8[2], ujB.x), q3 = mul2(S8[3], ujB.y);
        u64t q4 = mul2(S8[4], ujC.x), q5 = mul2(S8[5], ujC.y);
        u64t q6 = mul2(S8[6], ujD.x), q7 = mul2(S8[7], ujD.y);
        u64t qa = add2(add2(q0, q1), add2(q2, q3));
        u64t qb = add2(add2(q4, q5), add2(q6, q7));
        float qlo, qhi; upk2(add2(qa, qb), qlo, qhi);
        float su = qlo + qhi;

        // reductions over the 16-lane half
        float fl0, fl1, fl2, fl3;
        upk2(fA, fl0, fl1); upk2(fB, fl2, fl3);
        float tD = ui * su;
        float t0 = ui * fl0, t1 = ui * fl1, t2 = ui * fl2, t3 = ui * fl3;
#pragma unroll
        for (int o = 1; o <= 8; o <<= 1) {
            tD += __shfl_xor_sync(FULLM, tD, o);
            t0 += __shfl_xor_sync(FULLM, t0, o);
            t1 += __shfl_xor_sync(FULLM, t1, o);
            t2 += __shfl_xor_sync(FULLM, t2, o);
            t3 += __shfl_xor_sync(FULLM, t3, o);
        }

        float dn = an - tD;
        float rd = fast_rcp(dn);
        float wi = (vi - su) * rd;
        float zn0 = yv.x - t0, zn1 = yv.y - t1;
        float zn2 = yv.z - t2, zn3 = yv.w - t3;

        bool pr = (t < len) && (nrow >= s);
        if (pr) *pgW = wi;
        if (pr && il == 0)
            *(float4*)pgz = make_float4(zn0 * rd, zn1 * rd, zn2 * rd, zn3 * rd);
        llogd += pr ? __logf(dn) : 0.f;

        // rank-1 update: S += dn * w w^T
        float wj[16];
#pragma unroll
        for (int j = 0; j < 16; j++) wj[j] = __shfl_sync(FULLM, wi, b16 + j);
        float dwv = dn * wi;
        u64t dwP = pk2(dwv, dwv);
#pragma unroll
        for (int k = 0; k < 8; k++)
            S8[k] = fma2(dwP, pk2(wj[2*k], wj[2*k+1]), S8[k]);

        wprevP = pk2(wi, wi);
        zpA = pk2(zn0, zn1);
        zpB = pk2(zn2, zn3);

        bool adv = (t + 1 < len);
        int d16 = adv ? JDIM : 0;
        int d4  = adv ? RDIM : 0;
        pgW += d16; pgz += d4; nrow += adv ? 1 : 0;
    }

    if (active && il == 0) g_logd[chunk] = llogd;
}

// ---------------------------------------------------------------------------
// Kernel 2: backward solve. 2 chunks/warp (lane halves).
// Distance-1 register prefetch at occupancy 3 (unchanged from R13).
// ---------------------------------------------------------------------------
__global__ void __launch_bounds__(256, 3)
backward_kernel(const float* __restrict__ U, const float* __restrict__ P,
                const float* __restrict__ y, float* __restrict__ xout,
                int N, int C, int L)
{
    int warp = (blockIdx.x * blockDim.x + threadIdx.x) >> 5;
    int lane = threadIdx.x & 31;
    int il  = lane & 15;
    int half = lane >> 4;

    int chunk = 2 * warp + half;
    bool active = (chunk < C) && ((size_t)chunk * L < (size_t)N);
    int s = active ? chunk * L : 0;
    int e = min(s + L, N);

    float g0 = 0.f, g1 = 0.f, g2 = 0.f, g3 = 0.f;
    float acc0 = 0.f, acc1 = 0.f, acc2 = 0.f, acc3 = 0.f;

    if (active && e == N) {   // last chunk: x[N-1] = z[N-1]
        float4 z2 = *(const float4*)(g_z + (size_t)(N - 1) * RDIM);
        float4 yq = *(const float4*)(y + (size_t)(N - 1) * RDIM);
        if (il == 0) *(float4*)(xout + (size_t)(N - 1) * RDIM) = z2;
        acc0 = yq.x * z2.x; acc1 = yq.y * z2.y;
        acc2 = yq.z * z2.z; acc3 = yq.w * z2.w;
    }

    int n_start = min(e - 1 + OV, N - 2);
    int len = active ? max(0, n_start - s + 1) : 0;
    int w0 = max(0, n_start - e + 1);      // first stored iteration
    int T = max(len, __shfl_xor_sync(FULLM, len, 16));

    int row = (len > 0) ? n_start : 0;
    const float* pPi = P + (size_t)row * JDIM + il;
    const float* pUi = U + (size_t)(row + 1) * JDIM + il;
    const float* pz1 = g_z + (size_t)(row + 1) * RDIM;
    const float* pW  = g_W + (size_t)row * JDIM + il;
    const float* pzn = g_z + (size_t)row * RDIM;
    const float* pY  = y + (size_t)row * RDIM;
    float*       pX  = xout + (size_t)row * RDIM;

    float  pi = *pPi;
    float  u1 = *pUi;
    float4 z1 = *(const float4*)pz1;
    float  wi = *pW;
    float4 zn = *(const float4*)pzn;
    float4 yq = *(const float4*)pY;

#pragma unroll 1
    for (int t = 0; t < T; t++) {
        float cpi = pi, cu1 = u1, cwi = wi;
        float4 cz1 = z1, czn = zn, cyq = yq;

        bool adv = (t + 1 < len);
        int d16 = adv ? JDIM : 0;
        int d4  = adv ? RDIM : 0;
        pPi -= d16; pUi -= d16; pW -= d16;
        pz1 -= d4; pzn -= d4; pY -= d4;
        pi = *pPi; u1 = *pUi; z1 = *(const float4*)pz1;
        wi = *pW;  zn = *(const float4*)pzn; yq = *(const float4*)pY;

        g0 = cpi * (g0 + cu1 * cz1.x);
        g1 = cpi * (g1 + cu1 * cz1.y);
        g2 = cpi * (g2 + cu1 * cz1.z);
        g3 = cpi * (g3 + cu1 * cz1.w);

        float t0 = cwi * g0, t1 = cwi * g1, t2 = cwi * g2, t3 = cwi * g3;
#pragma unroll
        for (int o = 1; o <= 8; o <<= 1) {
            t0 += __shfl_xor_sync(FULLM, t0, o);
            t1 += __shfl_xor_sync(FULLM, t1, o);
            t2 += __shfl_xor_sync(FULLM, t2, o);
            t3 += __shfl_xor_sync(FULLM, t3, o);
        }

        float x0 = czn.x - t0, x1 = czn.y - t1;
        float x2 = czn.z - t2, x3 = czn.w - t3;

        bool pr = (t >= w0) && (t < len);
        if (pr && il == 0) *(float4*)pX = make_float4(x0, x1, x2, x3);
        acc0 += pr ? cyq.x * x0 : 0.f;
        acc1 += pr ? cyq.y * x1 : 0.f;
        acc2 += pr ? cyq.z * x2 : 0.f;
        acc3 += pr ? cyq.w * x3 : 0.f;
        pX -= d4;
    }

    if (active && il == 0)
        *(float4*)(g_yx + (size_t)chunk * RDIM) = make_float4(acc0, acc1, acc2, acc3);
}

// ---------------------------------------------------------------------------
// Kernel 3: finalize loglike (parallel, deterministic).
// ---------------------------------------------------------------------------
__global__ void finalize_kernel(float* __restrict__ out, int N, int Cf, int Cb)
{
    int wq = threadIdx.x >> 5;
    int lane = threadIdx.x & 31;

    double sl = 0.0;
    for (int c = lane; c < Cf; c += 32) sl += (double)g_logd[c];
#pragma unroll
    for (int o = 16; o > 0; o >>= 1) sl += __shfl_xor_sync(FULLM, sl, o);
    double norm = -0.5 * (sl + (double)N * log(6.283185307179586));

    double syx = 0.0;
    for (int c = lane; c < Cb; c += 32) syx += (double)g_yx[c * RDIM + wq];
#pragma unroll
    for (int o = 16; o > 0; o >>= 1) syx += __shfl_xor_sync(FULLM, syx, o);

    if (lane == 0 && wq < RDIM)
        out[(size_t)N * RDIM + wq] = (float)(norm - 0.5 * syx);
}

// ---------------------------------------------------------------------------
extern "C" void kernel_launch(void* const* d_in, const int* in_sizes, int n_in,
                              void* d_out, int out_size)
{
    const float* a = (const float*)d_in[0];
    const float* U = (const float*)d_in[1];
    const float* V = (const float*)d_in[2];
    const float* P = (const float*)d_in[3];
    const float* y = (const float*)d_in[4];
    float* out = (float*)d_out;

    int N = in_sizes[0];

    // forward: ~3552 warps x 2 chunks = ~7104 chunks (24 warps/SM)
    int ctF = 7104;
    int Lf = (N + ctF - 1) / ctF; if (Lf < 1) Lf = 1;
    int Cf = (N + Lf - 1) / Lf;
    if (Cf > MAXC) { Lf = (N + MAXC - 1) / MAXC; Cf = (N + Lf - 1) / Lf; }
    int warpsF = (Cf + 1) / 2;
    int blocksF = (warpsF * 32 + 255) / 256;

    // backward: ~3552 warps x 2 chunks = ~7104 chunks (24 warps/SM, occ 3)
    int ctB = 7104;
    int Lb = (N + ctB - 1) / ctB; if (Lb < 1) Lb = 1;
    int Cb = (N + Lb - 1) / Lb;
    if (Cb > MAXC) { Lb = (N + MAXC - 1) / MAXC; Cb = (N + Lb - 1) / Lb; }
    int warpsB = (Cb + 1) / 2;
    int blocksB = (warpsB * 32 + 255) / 256;

    factor_forward_kernel<<<blocksF, 256>>>(a, U, V, P, y, N, Cf, Lf);
    backward_kernel<<<blocksB, 256>>>(U, P, y, out, N, Cb, Lb);
    finalize_kernel<<<1, 128>>>(out, N, Cf, Cb);
}

// round 15
// speedup vs baseline: 1.0343x; 1.0343x over previous
#include <cuda_runtime.h>
#include <cstdint>

// celerite GP factor + solve + loglike. N=262144, J=16, R=4.
// Lane-split layout: 16 lanes per chunk, TWO chunks per warp (lane halves).
// Forward: loop-top loads + prefetch.global.L1 of next-row lines (zero-reg
// latency hiding). Backward: distance-1 register prefetch at occupancy 3.

#define JDIM 16
#define RDIM 4
#define OV   6
#define NMAX 262144
#define MAXC 16384
#define FULLM 0xffffffffu

typedef unsigned long long u64t;

__device__ float g_W[(size_t)NMAX * JDIM];
__device__ float g_z[(size_t)NMAX * RDIM];
__device__ float g_logd[MAXC];
__device__ float g_yx[MAXC * RDIM];

__device__ __forceinline__ float fast_rcp(float x) {
    float r;
    asm("rcp.approx.f32 %0, %1;" : "=f"(r) : "f"(x));
    r = r * (2.0f - x * r);
    return r;
}
__device__ __forceinline__ u64t pk2(float lo, float hi) {
    u64t r; asm("mov.b64 %0, {%1,%2};" : "=l"(r) : "f"(lo), "f"(hi)); return r;
}
__device__ __forceinline__ void upk2(u64t v, float& lo, float& hi) {
    asm("mov.b64 {%0,%1}, %2;" : "=f"(lo), "=f"(hi) : "l"(v));
}
__device__ __forceinline__ u64t mul2(u64t a, u64t b) {
    u64t r; asm("mul.rn.f32x2 %0, %1, %2;" : "=l"(r) : "l"(a), "l"(b)); return r;
}
__device__ __forceinline__ u64t add2(u64t a, u64t b) {
    u64t r; asm("add.rn.f32x2 %0, %1, %2;" : "=l"(r) : "l"(a), "l"(b)); return r;
}
__device__ __forceinline__ u64t fma2(u64t a, u64t b, u64t c) {
    u64t r; asm("fma.rn.f32x2 %0, %1, %2, %3;" : "=l"(r) : "l"(a), "l"(b), "l"(c)); return r;
}
__device__ __forceinline__ void pfL1(const void* p) {
    asm volatile("prefetch.global.L1 [%0];" :: "l"(p));
}

// ---------------------------------------------------------------------------
// Kernel 1: fused factorization + forward solve. 2 chunks/warp (lane halves).
// Lane i of each half holds full S row i (8 packed f32x2) and F[i][0..4).
// ---------------------------------------------------------------------------
__global__ void __launch_bounds__(256, 3)
factor_forward_kernel(const float* __restrict__ a, const float* __restrict__ U,
                      const float* __restrict__ V, const float* __restrict__ P,
                      const float* __restrict__ y, int N, int C, int L)
{
    int warp = (blockIdx.x * blockDim.x + threadIdx.x) >> 5;
    int lane = threadIdx.x & 31;
    int il  = lane & 15;
    int b16 = lane & 16;
    int half = lane >> 4;

    int chunk = 2 * warp + half;
    bool active = (chunk < C) && ((size_t)chunk * L < (size_t)N);
    int s = active ? chunk * L : 0;
    int e = min(s + L, N);
    int m0 = max(0, s - OV);
    int len = active ? (e - m0 - 1) : 0;
    int T = max(len, __shfl_xor_sync(FULLM, len, 16));

    // ---- init at row m0
    u64t S8[8];
    u64t fA, fB, zpA, zpB, wprevP;
    float llogd = 0.f;
    {
        float an = a[m0];
        float vi = V[(size_t)m0 * JDIM + il];
        float rd = fast_rcp(an);
        float wi = vi * rd;
        float wj[16];
#pragma unroll
        for (int j = 0; j < 16; j++) wj[j] = __shfl_sync(FULLM, wi, b16 + j);
        float dw = an * wi;
#pragma unroll
        for (int k = 0; k < 8; k++) S8[k] = pk2(dw * wj[2*k], dw * wj[2*k+1]);

        float4 y0 = *(const float4*)(y + (size_t)m0 * RDIM);
        zpA = pk2(y0.x, y0.y);
        zpB = pk2(y0.z, y0.w);
        fA = 0ull; fB = 0ull;
        wprevP = pk2(wi, wi);

        if (active && m0 == s) {   // chunk 0: store row 0
            g_W[(size_t)m0 * JDIM + il] = wi;
            if (il == 0) *(float4*)(g_z + (size_t)m0 * RDIM) =
                make_float4(y0.x * rd, y0.y * rd, y0.z * rd, y0.w * rd);
            llogd = __logf(an);
        }
    }

    // ---- pointers at first loop row n = m0+1 (P uses row n-1)
    int r1 = m0 + 1;
    const float* pP  = P + (size_t)m0 * JDIM;
    const float* pPi = pP + il;
    const float* pU  = U + (size_t)r1 * JDIM;
    const float* pUi = pU + il;
    const float* pVi = V + (size_t)r1 * JDIM + il;
    const float* pa  = a + r1;
    const float* pY  = y + (size_t)r1 * RDIM;
    float* pgW = g_W + (size_t)r1 * JDIM + il;
    float* pgz = g_z + (size_t)r1 * RDIM;
    int nrow = r1;

#pragma unroll 1
    for (int t = 0; t < T; t++) {
        // loads (full rows broadcast within half; scalars per lane)
        ulonglong2 pjA = *(const ulonglong2*)(pP);
        ulonglong2 pjB = *(const ulonglong2*)(pP + 4);
        ulonglong2 pjC = *(const ulonglong2*)(pP + 8);
        ulonglong2 pjD = *(const ulonglong2*)(pP + 12);
        float pi = *pPi;
        ulonglong2 ujA = *(const ulonglong2*)(pU);
        ulonglong2 ujB = *(const ulonglong2*)(pU + 4);
        ulonglong2 ujC = *(const ulonglong2*)(pU + 8);
        ulonglong2 ujD = *(const ulonglong2*)(pU + 12);
        float ui = *pUi;
        float vi = *pVi;
        float an = *pa;
        float4 yv = *(const float4*)(pY);

        // zero-register prefetch of next iteration's lines into L1
        pfL1(pP + JDIM);
        pfL1(pU + JDIM);
        pfL1(pVi + JDIM);
        pfL1(pY + RDIM);
        pfL1(pa + 1);

        u64t pis = pk2(pi, pi);

        // F recurrence
        fA = mul2(pis, fma2(wprevP, zpA, fA));
        fB = mul2(pis, fma2(wprevP, zpB, fB));

        // S decay (row i scaled by pi * pj elementwise)
        S8[0] = mul2(S8[0], mul2(pis, pjA.x));
        S8[1] = mul2(S8[1], mul2(pis, pjA.y));
        S8[2] = mul2(S8[2], mul2(pis, pjB.x));
        S8[3] = mul2(S8[3], mul2(pis, pjB.y));
        S8[4] = mul2(S8[4], mul2(pis, pjC.x));
        S8[5] = mul2(S8[5], mul2(pis, pjC.y));
        S8[6] = mul2(S8[6], mul2(pis, pjD.x));
        S8[7] = mul2(S8[7], mul2(pis, pjD.y));

        // su_i = S row . U row (fully lane-local)
        u64t q0 = mul2(S8[0], ujA.x), q1 = mul2(S8[1], ujA.y);
        u64t q2 = mul2(S8[2], ujB.x), q3 = mul2(S8[3], ujB.y);
        u64t q4 = mul2(S8[4], ujC.x), q5 = mul2(S8[5], ujC.y);
        u64t q6 = mul2(S8[6], ujD.x), q7 = mul2(S8[7], ujD.y);
        u64t qa = add2(add2(q0, q1), add2(q2, q3));
        u64t qb = add2(add2(q4, q5), add2(q6, q7));
        u64t qt = add2(qa, qb);
        float qlo, qhi; upk2(qt, qlo, qhi);
        float su = qlo + qhi;

        // reductions over the 16-lane half: tD = U.SU, t0..t3 = U.F
        float fl0, fl1, fl2, fl3;
        upk2(fA, fl0, fl1); upk2(fB, fl2, fl3);
        float tD = ui * su;
        float t0 = ui * fl0, t1 = ui * fl1, t2 = ui * fl2, t3 = ui * fl3;
#pragma unroll
        for (int o = 1; o <= 8; o <<= 1) {
            tD += __shfl_xor_sync(FULLM, tD, o);
            t0 += __shfl_xor_sync(FULLM, t0, o);
            t1 += __shfl_xor_sync(FULLM, t1, o);
            t2 += __shfl_xor_sync(FULLM, t2, o);
            t3 += __shfl_xor_sync(FULLM, t3, o);
        }

        float dn = an - tD;
        float rd = fast_rcp(dn);
        float wi = (vi - su) * rd;
        float zn0 = yv.x - t0, zn1 = yv.y - t1;
        float zn2 = yv.z - t2, zn3 = yv.w - t3;

        bool pr = (t < len) && (nrow >= s);
        if (pr) *pgW = wi;
        if (pr && il == 0)
            *(float4*)pgz = make_float4(zn0 * rd, zn1 * rd, zn2 * rd, zn3 * rd);
        llogd += pr ? __logf(dn) : 0.f;

        // rank-1 update: S += dn * w w^T
        float wj[16];
#pragma unroll
        for (int j = 0; j < 16; j++) wj[j] = __shfl_sync(FULLM, wi, b16 + j);
        float dwv = dn * wi;
        u64t dwP = pk2(dwv, dwv);
#pragma unroll
        for (int k = 0; k < 8; k++)
            S8[k] = fma2(dwP, pk2(wj[2*k], wj[2*k+1]), S8[k]);

        wprevP = pk2(wi, wi);
        zpA = pk2(zn0, zn1);
        zpB = pk2(zn2, zn3);

        // predicated pointer advance (freeze on tail)
        bool adv = (t + 1 < len);
        int d16 = adv ? JDIM : 0;
        int d4  = adv ? RDIM : 0;
        int d1  = adv ? 1 : 0;
        pP += d16; pPi += d16; pU += d16; pUi += d16; pVi += d16;
        pa += d1; pY += d4; pgW += d16; pgz += d4; nrow += d1;
    }

    if (active && il == 0) g_logd[chunk] = llogd;
}

// ---------------------------------------------------------------------------
// Kernel 2: backward solve. 2 chunks/warp (lane halves).
// Distance-1 register prefetch at occupancy 3 (unchanged from R13).
// ---------------------------------------------------------------------------
__global__ void __launch_bounds__(256, 3)
backward_kernel(const float* __restrict__ U, const float* __restrict__ P,
                const float* __restrict__ y, float* __restrict__ xout,
                int N, int C, int L)
{
    int warp = (blockIdx.x * blockDim.x + threadIdx.x) >> 5;
    int lane = threadIdx.x & 31;
    int il  = lane & 15;
    int half = lane >> 4;

    int chunk = 2 * warp + half;
    bool active = (chunk < C) && ((size_t)chunk * L < (size_t)N);
    int s = active ? chunk * L : 0;
    int e = min(s + L, N);

    float g0 = 0.f, g1 = 0.f, g2 = 0.f, g3 = 0.f;
    float acc0 = 0.f, acc1 = 0.f, acc2 = 0.f, acc3 = 0.f;

    if (active && e == N) {   // last chunk: x[N-1] = z[N-1]
        float4 z2 = *(const float4*)(g_z + (size_t)(N - 1) * RDIM);
        float4 yq = *(const float4*)(y + (size_t)(N - 1) * RDIM);
        if (il == 0) *(float4*)(xout + (size_t)(N - 1) * RDIM) = z2;
        acc0 = yq.x * z2.x; acc1 = yq.y * z2.y;
        acc2 = yq.z * z2.z; acc3 = yq.w * z2.w;
    }

    int n_start = min(e - 1 + OV, N - 2);
    int len = active ? max(0, n_start - s + 1) : 0;
    int w0 = max(0, n_start - e + 1);      // first stored iteration
    int T = max(len, __shfl_xor_sync(FULLM, len, 16));

    int row = (len > 0) ? n_start : 0;
    const float* pPi = P + (size_t)row * JDIM + il;
    const float* pUi = U + (size_t)(row + 1) * JDIM + il;
    const float* pz1 = g_z + (size_t)(row + 1) * RDIM;
    const float* pW  = g_W + (size_t)row * JDIM + il;
    const float* pzn = g_z + (size_t)row * RDIM;
    const float* pY  = y + (size_t)row * RDIM;
    float*       pX  = xout + (size_t)row * RDIM;

    float  pi = *pPi;
    float  u1 = *pUi;
    float4 z1 = *(const float4*)pz1;
    float  wi = *pW;
    float4 zn = *(const float4*)pzn;
    float4 yq = *(const float4*)pY;

#pragma unroll 1
    for (int t = 0; t < T; t++) {
        float cpi = pi, cu1 = u1, cwi = wi;
        float4 cz1 = z1, czn = zn, cyq = yq;

        bool adv = (t + 1 < len);
        int d16 = adv ? JDIM : 0;
        int d4  = adv ? RDIM : 0;
        pPi -= d16; pUi -= d16; pW -= d16;
        pz1 -= d4; pzn -= d4; pY -= d4;
        pi = *pPi; u1 = *pUi; z1 = *(const float4*)pz1;
        wi = *pW;  zn = *(const float4*)pzn; yq = *(const float4*)pY;

        g0 = cpi * (g0 + cu1 * cz1.x);
        g1 = cpi * (g1 + cu1 * cz1.y);
        g2 = cpi * (g2 + cu1 * cz1.z);
        g3 = cpi * (g3 + cu1 * cz1.w);

        float t0 = cwi * g0, t1 = cwi * g1, t2 = cwi * g2, t3 = cwi * g3;
#pragma unroll
        for (int o = 1; o <= 8; o <<= 1) {
            t0 += __shfl_xor_sync(FULLM, t0, o);
            t1 += __shfl_xor_sync(FULLM, t1, o);
            t2 += __shfl_xor_sync(FULLM, t2, o);
            t3 += __shfl_xor_sync(FULLM, t3, o);
        }

        float x0 = czn.x - t0, x1 = czn.y - t1;
        float x2 = czn.z - t2, x3 = czn.w - t3;

        bool pr = (t >= w0) && (t < len);
        if (pr && il == 0) *(float4*)pX = make_float4(x0, x1, x2, x3);
        acc0 += pr ? cyq.x * x0 : 0.f;
        acc1 += pr ? cyq.y * x1 : 0.f;
        acc2 += pr ? cyq.z * x2 : 0.f;
        acc3 += pr ? cyq.w * x3 : 0.f;
        pX -= d4;
    }

    if (active && il == 0)
        *(float4*)(g_yx + (size_t)chunk * RDIM) = make_float4(acc0, acc1, acc2, acc3);
}

// ---------------------------------------------------------------------------
// Kernel 3: finalize loglike (parallel, deterministic).
// ---------------------------------------------------------------------------
__global__ void finalize_kernel(float* __restrict__ out, int N, int Cf, int Cb)
{
    int wq = threadIdx.x >> 5;
    int lane = threadIdx.x & 31;

    double sl = 0.0;
    for (int c = lane; c < Cf; c += 32) sl += (double)g_logd[c];
#pragma unroll
    for (int o = 16; o > 0; o >>= 1) sl += __shfl_xor_sync(FULLM, sl, o);
    double norm = -0.5 * (sl + (double)N * log(6.283185307179586));

    double syx = 0.0;
    for (int c = lane; c < Cb; c += 32) syx += (double)g_yx[c * RDIM + wq];
#pragma unroll
    for (int o = 16; o > 0; o >>= 1) syx += __shfl_xor_sync(FULLM, syx, o);

    if (lane == 0 && wq < RDIM)
        out[(size_t)N * RDIM + wq] = (float)(norm - 0.5 * syx);
}

// ---------------------------------------------------------------------------
extern "C" void kernel_launch(void* const* d_in, const int* in_sizes, int n_in,
                              void* d_out, int out_size)
{
    const float* a = (const float*)d_in[0];
    const float* U = (const float*)d_in[1];
    const float* V = (const float*)d_in[2];
    const float* P = (const float*)d_in[3];
    const float* y = (const float*)d_in[4];
    float* out = (float*)d_out;

    int N = in_sizes[0];

    // forward: ~3552 warps x 2 chunks = ~7104 chunks (24 warps/SM)
    int ctF = 7104;
    int Lf = (N + ctF - 1) / ctF; if (Lf < 1) Lf = 1;
    int Cf = (N + Lf - 1) / Lf;
    if (Cf > MAXC) { Lf = (N + MAXC - 1) / MAXC; Cf = (N + Lf - 1) / Lf; }
    int warpsF = (Cf + 1) / 2;
    int blocksF = (warpsF * 32 + 255) / 256;

    // backward: ~3552 warps x 2 chunks = ~7104 chunks (24 warps/SM, occ 3)
    int ctB = 7104;
    int Lb = (N + ctB - 1) / ctB; if (Lb < 1) Lb = 1;
    int Cb = (N + Lb - 1) / Lb;
    if (Cb > MAXC) { Lb = (N + MAXC - 1) / MAXC; Cb = (N + Lb - 1) / Lb; }
    int warpsB = (Cb + 1) / 2;
    int blocksB = (warpsB * 32 + 255) / 256;

    factor_forward_kernel<<<blocksF, 256>>>(a, U, V, P, y, N, Cf, Lf);
    backward_kernel<<<blocksB, 256>>>(U, P, y, out, N, Cb, Lb);
    finalize_kernel<<<1, 128>>>(out, N, Cf, Cb);
}

// round 16
// speedup vs baseline: 1.1950x; 1.1553x over previous
#include <cuda_runtime.h>
#include <cstdint>

// celerite GP factor + solve + loglike. N=262144, J=16, R=4.
// Lane-split layout: 16 lanes per chunk, TWO chunks per warp (lane halves).
// Forward: R13 structure (loop-top loads, predicated pointer advance).
// Backward: TRANSPOSED G layout — lane (r=il&3, q=il>>2) owns G[4q..4q+3][r];
// reduction is 2 shuffles (xor4, xor8) instead of 16.

#define JDIM 16
#define RDIM 4
#define OV   6
#define NMAX 262144
#define MAXC 16384
#define FULLM 0xffffffffu

typedef unsigned long long u64t;

__device__ float g_W[(size_t)NMAX * JDIM];
__device__ float g_z[(size_t)NMAX * RDIM];
__device__ float g_logd[MAXC];
__device__ float g_yx[MAXC * RDIM];

__device__ __forceinline__ float fast_rcp(float x) {
    float r;
    asm("rcp.approx.f32 %0, %1;" : "=f"(r) : "f"(x));
    r = r * (2.0f - x * r);
    return r;
}
__device__ __forceinline__ u64t pk2(float lo, float hi) {
    u64t r; asm("mov.b64 %0, {%1,%2};" : "=l"(r) : "f"(lo), "f"(hi)); return r;
}
__device__ __forceinline__ void upk2(u64t v, float& lo, float& hi) {
    asm("mov.b64 {%0,%1}, %2;" : "=f"(lo), "=f"(hi) : "l"(v));
}
__device__ __forceinline__ u64t mul2(u64t a, u64t b) {
    u64t r; asm("mul.rn.f32x2 %0, %1, %2;" : "=l"(r) : "l"(a), "l"(b)); return r;
}
__device__ __forceinline__ u64t add2(u64t a, u64t b) {
    u64t r; asm("add.rn.f32x2 %0, %1, %2;" : "=l"(r) : "l"(a), "l"(b)); return r;
}
__device__ __forceinline__ u64t fma2(u64t a, u64t b, u64t c) {
    u64t r; asm("fma.rn.f32x2 %0, %1, %2, %3;" : "=l"(r) : "l"(a), "l"(b), "l"(c)); return r;
}

// ---------------------------------------------------------------------------
// Kernel 1: fused factorization + forward solve. 2 chunks/warp (lane halves).
// (R13 structure verbatim.)
// ---------------------------------------------------------------------------
__global__ void __launch_bounds__(256, 3)
factor_forward_kernel(const float* __restrict__ a, const float* __restrict__ U,
                      const float* __restrict__ V, const float* __restrict__ P,
                      const float* __restrict__ y, int N, int C, int L)
{
    int warp = (blockIdx.x * blockDim.x + threadIdx.x) >> 5;
    int lane = threadIdx.x & 31;
    int il  = lane & 15;
    int b16 = lane & 16;
    int half = lane >> 4;

    int chunk = 2 * warp + half;
    bool active = (chunk < C) && ((size_t)chunk * L < (size_t)N);
    int s = active ? chunk * L : 0;
    int e = min(s + L, N);
    int m0 = max(0, s - OV);
    int len = active ? (e - m0 - 1) : 0;
    int T = max(len, __shfl_xor_sync(FULLM, len, 16));

    // ---- init at row m0
    u64t S8[8];
    u64t fA, fB, zpA, zpB, wprevP;
    float llogd = 0.f;
    {
        float an = a[m0];
        float vi = V[(size_t)m0 * JDIM + il];
        float rd = fast_rcp(an);
        float wi = vi * rd;
        float wj[16];
#pragma unroll
        for (int j = 0; j < 16; j++) wj[j] = __shfl_sync(FULLM, wi, b16 + j);
        float dw = an * wi;
#pragma unroll
        for (int k = 0; k < 8; k++) S8[k] = pk2(dw * wj[2*k], dw * wj[2*k+1]);

        float4 y0 = *(const float4*)(y + (size_t)m0 * RDIM);
        zpA = pk2(y0.x, y0.y);
        zpB = pk2(y0.z, y0.w);
        fA = 0ull; fB = 0ull;
        wprevP = pk2(wi, wi);

        if (active && m0 == s) {   // chunk 0: store row 0
            g_W[(size_t)m0 * JDIM + il] = wi;
            if (il == 0) *(float4*)(g_z + (size_t)m0 * RDIM) =
                make_float4(y0.x * rd, y0.y * rd, y0.z * rd, y0.w * rd);
            llogd = __logf(an);
        }
    }

    // ---- pointers at first loop row n = m0+1 (P uses row n-1)
    int r1 = m0 + 1;
    const float* pP  = P + (size_t)m0 * JDIM;
    const float* pPi = pP + il;
    const float* pU  = U + (size_t)r1 * JDIM;
    const float* pUi = pU + il;
    const float* pVi = V + (size_t)r1 * JDIM + il;
    const float* pa  = a + r1;
    const float* pY  = y + (size_t)r1 * RDIM;
    float* pgW = g_W + (size_t)r1 * JDIM + il;
    float* pgz = g_z + (size_t)r1 * RDIM;
    int nrow = r1;

#pragma unroll 1
    for (int t = 0; t < T; t++) {
        ulonglong2 pjA = *(const ulonglong2*)(pP);
        ulonglong2 pjB = *(const ulonglong2*)(pP + 4);
        ulonglong2 pjC = *(const ulonglong2*)(pP + 8);
        ulonglong2 pjD = *(const ulonglong2*)(pP + 12);
        float pi = *pPi;
        ulonglong2 ujA = *(const ulonglong2*)(pU);
        ulonglong2 ujB = *(const ulonglong2*)(pU + 4);
        ulonglong2 ujC = *(const ulonglong2*)(pU + 8);
        ulonglong2 ujD = *(const ulonglong2*)(pU + 12);
        float ui = *pUi;
        float vi = *pVi;
        float an = *pa;
        float4 yv = *(const float4*)(pY);

        u64t pis = pk2(pi, pi);

        fA = mul2(pis, fma2(wprevP, zpA, fA));
        fB = mul2(pis, fma2(wprevP, zpB, fB));

        S8[0] = mul2(S8[0], mul2(pis, pjA.x));
        S8[1] = mul2(S8[1], mul2(pis, pjA.y));
        S8[2] = mul2(S8[2], mul2(pis, pjB.x));
        S8[3] = mul2(S8[3], mul2(pis, pjB.y));
        S8[4] = mul2(S8[4], mul2(pis, pjC.x));
        S8[5] = mul2(S8[5], mul2(pis, pjC.y));
        S8[6] = mul2(S8[6], mul2(pis, pjD.x));
        S8[7] = mul2(S8[7], mul2(pis, pjD.y));

        u64t q0 = mul2(S8[0], ujA.x), q1 = mul2(S8[1], ujA.y);
        u64t q2 = mul2(S8[2], ujB.x), q3 = mul2(S8[3], ujB.y);
        u64t q4 = mul2(S8[4], ujC.x), q5 = mul2(S8[5], ujC.y);
        u64t q6 = mul2(S8[6], ujD.x), q7 = mul2(S8[7], ujD.y);
        u64t qa = add2(add2(q0, q1), add2(q2, q3));
        u64t qb = add2(add2(q4, q5), add2(q6, q7));
        u64t qt = add2(qa, qb);
        float qlo, qhi; upk2(qt, qlo, qhi);
        float su = qlo + qhi;

        float fl0, fl1, fl2, fl3;
        upk2(fA, fl0, fl1); upk2(fB, fl2, fl3);
        float tD = ui * su;
        float t0 = ui * fl0, t1 = ui * fl1, t2 = ui * fl2, t3 = ui * fl3;
#pragma unroll
        for (int o = 1; o <= 8; o <<= 1) {
            tD += __shfl_xor_sync(FULLM, tD, o);
            t0 += __shfl_xor_sync(FULLM, t0, o);
            t1 += __shfl_xor_sync(FULLM, t1, o);
            t2 += __shfl_xor_sync(FULLM, t2, o);
            t3 += __shfl_xor_sync(FULLM, t3, o);
        }

        float dn = an - tD;
        float rd = fast_rcp(dn);
        float wi = (vi - su) * rd;
        float zn0 = yv.x - t0, zn1 = yv.y - t1;
        float zn2 = yv.z - t2, zn3 = yv.w - t3;

        bool pr = (t < len) && (nrow >= s);
        if (pr) *pgW = wi;
        if (pr && il == 0)
            *(float4*)pgz = make_float4(zn0 * rd, zn1 * rd, zn2 * rd, zn3 * rd);
        llogd += pr ? __logf(dn) : 0.f;

        float wj[16];
#pragma unroll
        for (int j = 0; j < 16; j++) wj[j] = __shfl_sync(FULLM, wi, b16 + j);
        float dwv = dn * wi;
        u64t dwP = pk2(dwv, dwv);
#pragma unroll
        for (int k = 0; k < 8; k++)
            S8[k] = fma2(dwP, pk2(wj[2*k], wj[2*k+1]), S8[k]);

        wprevP = pk2(wi, wi);
        zpA = pk2(zn0, zn1);
        zpB = pk2(zn2, zn3);

        bool adv = (t + 1 < len);
        int d16 = adv ? JDIM : 0;
        int d4  = adv ? RDIM : 0;
        int d1  = adv ? 1 : 0;
        pP += d16; pPi += d16; pU += d16; pUi += d16; pVi += d16;
        pa += d1; pY += d4; pgW += d16; pgz += d4; nrow += d1;
    }

    if (active && il == 0) g_logd[chunk] = llogd;
}

// ---------------------------------------------------------------------------
// Kernel 2: backward solve. 2 chunks/warp (lane halves), TRANSPOSED G:
// lane (r=il&3, q=il>>2) owns G[4q..4q+3][r]. Reduction = xor4 + xor8 only.
// Distance-1 register prefetch at occupancy 3.
// ---------------------------------------------------------------------------
__global__ void __launch_bounds__(256, 3)
backward_kernel(const float* __restrict__ U, const float* __restrict__ P,
                const float* __restrict__ y, float* __restrict__ xout,
                int N, int C, int L)
{
    int warp = (blockIdx.x * blockDim.x + threadIdx.x) >> 5;
    int lane = threadIdx.x & 31;
    int il  = lane & 15;
    int half = lane >> 4;
    int r = il & 3;
    int q = il >> 2;

    int chunk = 2 * warp + half;
    bool active = (chunk < C) && ((size_t)chunk * L < (size_t)N);
    int s = active ? chunk * L : 0;
    int e = min(s + L, N);

    float G0 = 0.f, G1 = 0.f, G2 = 0.f, G3 = 0.f;   // G[4q+k][r]
    float acc = 0.f;                                  // sum y_r x_r (dup x4 over q)

    if (active && e == N) {   // last chunk: x[N-1] = z[N-1]
        float zr = g_z[(size_t)(N - 1) * RDIM + r];
        float yr = y[(size_t)(N - 1) * RDIM + r];
        if (q == 0) xout[(size_t)(N - 1) * RDIM + r] = zr;
        acc = yr * zr;
    }

    int n_start = min(e - 1 + OV, N - 2);
    int len = active ? max(0, n_start - s + 1) : 0;
    int w0 = max(0, n_start - e + 1);      // first stored iteration
    int T = max(len, __shfl_xor_sync(FULLM, len, 16));

    int row = (len > 0) ? n_start : 0;
    const float* pPq = P + (size_t)row * JDIM + q * 4;
    const float* pUq = U + (size_t)(row + 1) * JDIM + q * 4;
    const float* pWq = g_W + (size_t)row * JDIM + q * 4;
    const float* pz1 = g_z + (size_t)(row + 1) * RDIM + r;
    const float* pzn = g_z + (size_t)row * RDIM + r;
    const float* pyr = y + (size_t)row * RDIM + r;
    float*       pX  = xout + (size_t)row * RDIM + r;

    // preload iteration 0
    float4 Pq = *(const float4*)pPq;
    float4 Uq = *(const float4*)pUq;
    float4 Wq = *(const float4*)pWq;
    float z1r = *pz1;
    float znr = *pzn;
    float yr  = *pyr;

#pragma unroll 1
    for (int t = 0; t < T; t++) {
        float4 cP = Pq, cU = Uq, cW = Wq;
        float cz1 = z1r, czn = znr, cy = yr;

        // distance-1 prefetch (frozen on tail)
        bool adv = (t + 1 < len);
        int d16 = adv ? JDIM : 0;
        int d4  = adv ? RDIM : 0;
        pPq -= d16; pUq -= d16; pWq -= d16;
        pz1 -= d4; pzn -= d4; pyr -= d4;
        Pq = *(const float4*)pPq;
        Uq = *(const float4*)pUq;
        Wq = *(const float4*)pWq;
        z1r = *pz1; znr = *pzn; yr = *pyr;

        // G update (4 elements of column r, rows 4q..4q+3)
        G0 = cP.x * fmaf(cU.x, cz1, G0);
        G1 = cP.y * fmaf(cU.y, cz1, G1);
        G2 = cP.z * fmaf(cU.z, cz1, G2);
        G3 = cP.w * fmaf(cU.w, cz1, G3);

        // partial W.G over this lane's 4 rows, then reduce over q (2 shfls)
        float p = fmaf(cW.w, G3, fmaf(cW.z, G2, fmaf(cW.y, G1, cW.x * G0)));
        p += __shfl_xor_sync(FULLM, p, 4);
        p += __shfl_xor_sync(FULLM, p, 8);

        float xr = czn - p;
        bool pr = (t >= w0) && (t < len);
        if (pr && q == 0) *pX = xr;
        acc += pr ? cy * xr : 0.f;
        pX -= d4;
    }

    if (active && q == 0) g_yx[(size_t)chunk * RDIM + r] = acc;
}

// ---------------------------------------------------------------------------
// Kernel 3: finalize loglike (parallel, deterministic).
// ---------------------------------------------------------------------------
__global__ void finalize_kernel(float* __restrict__ out, int N, int Cf, int Cb)
{
    int wq = threadIdx.x >> 5;
    int lane = threadIdx.x & 31;

    double sl = 0.0;
    for (int c = lane; c < Cf; c += 32) sl += (double)g_logd[c];
#pragma unroll
    for (int o = 16; o > 0; o >>= 1) sl += __shfl_xor_sync(FULLM, sl, o);
    double norm = -0.5 * (sl + (double)N * log(6.283185307179586));

    double syx = 0.0;
    for (int c = lane; c < Cb; c += 32) syx += (double)g_yx[c * RDIM + wq];
#pragma unroll
    for (int o = 16; o > 0; o >>= 1) syx += __shfl_xor_sync(FULLM, syx, o);

    if (lane == 0 && wq < RDIM)
        out[(size_t)N * RDIM + wq] = (float)(norm - 0.5 * syx);
}

// ---------------------------------------------------------------------------
extern "C" void kernel_launch(void* const* d_in, const int* in_sizes, int n_in,
                              void* d_out, int out_size)
{
    const float* a = (const float*)d_in[0];
    const float* U = (const float*)d_in[1];
    const float* V = (const float*)d_in[2];
    const float* P = (const float*)d_in[3];
    const float* y = (const float*)d_in[4];
    float* out = (float*)d_out;

    int N = in_sizes[0];

    // forward: ~3552 warps x 2 chunks = ~7104 chunks (24 warps/SM)
    int ctF = 7104;
    int Lf = (N + ctF - 1) / ctF; if (Lf < 1) Lf = 1;
    int Cf = (N + Lf - 1) / Lf;
    if (Cf > MAXC) { Lf = (N + MAXC - 1) / MAXC; Cf = (N + Lf - 1) / Lf; }
    int warpsF = (Cf + 1) / 2;
    int blocksF = (warpsF * 32 + 255) / 256;

    // backward: ~3552 warps x 2 chunks = ~7104 chunks (24 warps/SM, occ 3)
    int ctB = 7104;
    int Lb = (N + ctB - 1) / ctB; if (Lb < 1) Lb = 1;
    int Cb = (N + Lb - 1) / Lb;
    if (Cb > MAXC) { Lb = (N + MAXC - 1) / MAXC; Cb = (N + Lb - 1) / Lb; }
    int warpsB = (Cb + 1) / 2;
    int blocksB = (warpsB * 32 + 255) / 256;

    factor_forward_kernel<<<blocksF, 256>>>(a, U, V, P, y, N, Cf, Lf);
    backward_kernel<<<blocksB, 256>>>(U, P, y, out, N, Cb, Lb);
    finalize_kernel<<<1, 128>>>(out, N, Cf, Cb);
}